// round 13
// baseline (speedup 1.0000x reference)
#include <cuda_runtime.h>
#include <cuda_bf16.h>

// MatrixFactorization: out[r] = dot(concat(Wd[dow],Wt[time],Wm[month],Wdy[day]), W_item[dest])
// N=1048576, NUM_FACTOR=128, NUM_DIM=32.
//
// R13: element mapping float2/lane in two halves to avoid within-LDG replay
// cost (2.07 cyc/wf) in favor of cross-LDG wavefronts (1.0 cyc/wf):
//  - item row: 2x LDG.64 (2 lines each) instead of 1x LDG.128 (4 lines).
//  - user: lane covers concat pos lane*2 (table lane>>4) and 64+lane*2
//    (table 2+(lane>>4)); each user LDG.64 touches 2 lines.
//  - idx loads: per-half-warp arrays -> 2 lines per instruction.
// Keeps R10's 2-batch software pipeline and merged 16-shuffle reduction.

#define WARPS_PER_BLOCK 4
#define THREADS (WARPS_PER_BLOCK * 32)
#define BATCH 8
#define ROWS_PER_WARP 16   // 2 pipelined batches of 8

struct IdxB { int siA[BATCH]; int siB[BATCH]; int di[BATCH]; };

__device__ __forceinline__ void load_idx(const int* __restrict__ arrA,
                                         const int* __restrict__ arrB,
                                         const int* __restrict__ dest,
                                         int rb, IdxB& o)
{
    const int4 a0 = *reinterpret_cast<const int4*>(arrA + rb);
    const int4 a1 = *reinterpret_cast<const int4*>(arrA + rb + 4);
    const int4 b0 = *reinterpret_cast<const int4*>(arrB + rb);
    const int4 b1 = *reinterpret_cast<const int4*>(arrB + rb + 4);
    const int4 d0 = *reinterpret_cast<const int4*>(dest + rb);
    const int4 d1 = *reinterpret_cast<const int4*>(dest + rb + 4);
    o.siA[0]=a0.x; o.siA[1]=a0.y; o.siA[2]=a0.z; o.siA[3]=a0.w;
    o.siA[4]=a1.x; o.siA[5]=a1.y; o.siA[6]=a1.z; o.siA[7]=a1.w;
    o.siB[0]=b0.x; o.siB[1]=b0.y; o.siB[2]=b0.z; o.siB[3]=b0.w;
    o.siB[4]=b1.x; o.siB[5]=b1.y; o.siB[6]=b1.z; o.siB[7]=b1.w;
    o.di[0]=d0.x; o.di[1]=d0.y; o.di[2]=d0.z; o.di[3]=d0.w;
    o.di[4]=d1.x; o.di[5]=d1.y; o.di[6]=d1.z; o.di[7]=d1.w;
}

__device__ __forceinline__ void load_data(const float* __restrict__ WA,
                                          const float* __restrict__ WB,
                                          const float* __restrict__ Witem,
                                          const IdxB& ix, int h2, int lane2,
                                          float2* u1, float2* u2,
                                          float2* v1, float2* v2)
{
    // Item halves first: the L2-latency-critical loads, 2 lines per LDG.64.
#pragma unroll
    for (int i = 0; i < BATCH; i++) {
        const int ibase = ix.di[i] * 128;
        v1[i] = *reinterpret_cast<const float2*>(Witem + ibase + lane2);
        v2[i] = *reinterpret_cast<const float2*>(Witem + ibase + 64 + lane2);
    }
    // User halves: 2 lines per LDG.64 (one table per half-warp).
#pragma unroll
    for (int i = 0; i < BATCH; i++) {
        u1[i] = *reinterpret_cast<const float2*>(WA + (ix.siA[i] * 32 + h2));
        u2[i] = *reinterpret_cast<const float2*>(WB + (ix.siB[i] * 32 + h2));
    }
}

__device__ __forceinline__ void reduce_store(const float2* u1, const float2* u2,
                                             const float2* v1, const float2* v2,
                                             float* __restrict__ out, int rb,
                                             int lane, int rowid, bool is_writer)
{
    float s[BATCH];
#pragma unroll
    for (int i = 0; i < BATCH; i++) {
        float acc = u1[i].x * v1[i].x;
        acc = fmaf(u1[i].y, v1[i].y, acc);
        acc = fmaf(u2[i].x, v2[i].x, acc);
        acc = fmaf(u2[i].y, v2[i].y, acc);
        s[i] = acc;
    }
#pragma unroll
    for (int i = 0; i < BATCH; i++)
        s[i] += __shfl_xor_sync(0xFFFFFFFFu, s[i], 16);
    float t[4];
#pragma unroll
    for (int i = 0; i < 4; i++)
        t[i] = (lane < 16) ? s[2 * i] : s[2 * i + 1];
#pragma unroll
    for (int i = 0; i < 4; i++)
        t[i] += __shfl_xor_sync(0xFFFFFFFFu, t[i], 8);
    float q[2];
#pragma unroll
    for (int i = 0; i < 2; i++)
        q[i] = ((lane & 8) == 0) ? t[2 * i] : t[2 * i + 1];
#pragma unroll
    for (int i = 0; i < 2; i++)
        q[i] += __shfl_xor_sync(0xFFFFFFFFu, q[i], 4);
    float z = ((lane & 4) == 0) ? q[0] : q[1];
    z += __shfl_xor_sync(0xFFFFFFFFu, z, 2);
    z += __shfl_xor_sync(0xFFFFFFFFu, z, 1);

    if (is_writer) out[rb + rowid] = z;
}

__global__ __launch_bounds__(THREADS)
void mf_kernel(const int* __restrict__ dow,
               const int* __restrict__ tim,
               const int* __restrict__ mon,
               const int* __restrict__ day,
               const int* __restrict__ dest,
               const float* __restrict__ Wdow,
               const float* __restrict__ Wtim,
               const float* __restrict__ Wmon,
               const float* __restrict__ Wday,
               const float* __restrict__ Witem,
               float* __restrict__ out,
               int n)
{
    const int warp_id = blockIdx.x * WARPS_PER_BLOCK + (threadIdx.x >> 5);
    const int lane = threadIdx.x & 31;
    const int g = lane >> 4;          // 0: first-half tables, 1: second
    const int h2 = (lane & 15) * 2;   // float offset within 32-dim embedding
    const int lane2 = lane * 2;       // item float offset within half-row

    // First 64 concat positions come from {dow,tim}; last 64 from {mon,day}.
    const float* __restrict__ WA = (g == 0) ? Wdow : Wtim;
    const float* __restrict__ WB = (g == 0) ? Wmon : Wday;
    const int* __restrict__ arrA = (g == 0) ? dow : tim;
    const int* __restrict__ arrB = (g == 0) ? mon : day;

    const int rowid = ((lane >> 4) & 1) | (((lane >> 3) & 1) << 1) | (((lane >> 2) & 1) << 2);
    const bool is_writer = ((lane & 3) == 0);

    const int base = warp_id * ROWS_PER_WARP;
    if (base >= n) return;
    const int rb0 = base;
    const int rb1 = base + BATCH;

    IdxB ix0, ix1;
    float2 u1a[BATCH], u2a[BATCH], v1a[BATCH], v2a[BATCH];
    float2 u1b[BATCH], u2b[BATCH], v1b[BATCH], v2b[BATCH];

    load_idx(arrA, arrB, dest, rb0, ix0);                       // idx0
    load_data(WA, WB, Witem, ix0, h2, lane2, u1a, u2a, v1a, v2a); // data0 in flight
    load_idx(arrA, arrB, dest, rb1, ix1);                       // idx1 overlaps

    reduce_store(u1a, u2a, v1a, v2a, out, rb0, lane, rowid, is_writer);

    load_data(WA, WB, Witem, ix1, h2, lane2, u1b, u2b, v1b, v2b); // idx1 resident
    reduce_store(u1b, u2b, v1b, v2b, out, rb1, lane, rowid, is_writer);
}

extern "C" void kernel_launch(void* const* d_in, const int* in_sizes, int n_in,
                              void* d_out, int out_size)
{
    const int*   dow   = (const int*)d_in[0];
    const int*   tim   = (const int*)d_in[1];
    const int*   mon   = (const int*)d_in[2];
    const int*   day   = (const int*)d_in[3];
    const int*   dest  = (const int*)d_in[4];
    const float* Wdow  = (const float*)d_in[5];
    const float* Wtim  = (const float*)d_in[6];
    const float* Wmon  = (const float*)d_in[7];
    const float* Wday  = (const float*)d_in[8];
    const float* Witem = (const float*)d_in[9];
    float* out = (float*)d_out;

    const int n = in_sizes[0];
    const int rows_per_block = WARPS_PER_BLOCK * ROWS_PER_WARP;  // 64
    const int grid = (n + rows_per_block - 1) / rows_per_block;

    mf_kernel<<<grid, THREADS>>>(dow, tim, mon, day, dest,
                                 Wdow, Wtim, Wmon, Wday, Witem, out, n);
}